// round 11
// baseline (speedup 1.0000x reference)
#include <cuda_runtime.h>

// MaxPool2d k=2 s=2 valid, (32,64,224,224) fp32 -> (32,64,112,112).
// R10 = R9 body (8 front-batched independent LDG.128 over a 4-row x 8-col
// input patch, 2 STG.128, plain cache ops — the best-measured configuration)
// with __launch_bounds__(256, 8): forces regs <= 32 so 8 CTAs/SM fit ->
// 100% theoretical occupancy (R9 was 36 regs -> 7 CTAs/SM). Deeper resident
// warp pool to cover DRAM latency at wave tails — the only remaining idle
// DRAM window. Pure HBM stream: 411 MB read + 103 MB write, zero reuse,
// all accesses 16B-aligned. Wall-clock is pinned at the HBM roofline
// (~6.8 TB/s steady state); this is the final occupancy probe.

#define NC_TOTAL   2048              // 32 * 64
#define IH         224
#define IW         224
#define OH         112
#define OW         112
#define IN_PLANE   (IH * IW)         // 50176
#define OUT_PLANE  (OH * OW)         // 12544
#define GROUPS_W   (OW / 4)          // 28 float4 groups per output row
#define ROWPAIRS   (OH / 2)          // 56 output-row pairs
#define TOTAL_THREADS (NC_TOTAL * ROWPAIRS * GROUPS_W)   // 3,211,264

__device__ __forceinline__ float4 pool2(const float4 a0, const float4 a1,
                                        const float4 b0, const float4 b1) {
    float4 o;
    o.x = fmaxf(fmaxf(a0.x, a0.y), fmaxf(b0.x, b0.y));
    o.y = fmaxf(fmaxf(a0.z, a0.w), fmaxf(b0.z, b0.w));
    o.z = fmaxf(fmaxf(a1.x, a1.y), fmaxf(b1.x, b1.y));
    o.w = fmaxf(fmaxf(a1.z, a1.w), fmaxf(b1.z, b1.w));
    return o;
}

__global__ __launch_bounds__(256, 8)
void maxpool2d_k2s2_occ_kernel(const float* __restrict__ in, float* __restrict__ out) {
    int idx = blockIdx.x * blockDim.x + threadIdx.x;
    if (idx >= TOTAL_THREADS) return;

    int w8  = idx % GROUPS_W;            // output col group (4 cols -> 8 input cols)
    int t   = idx / GROUPS_W;
    int ohp = t % ROWPAIRS;              // which pair of output rows
    int nc  = t / ROWPAIRS;

    const int rstep = IW / 4;            // 56 float4 per input row
    const float4* r0 = reinterpret_cast<const float4*>(
        in + (size_t)nc * IN_PLANE + (size_t)(ohp * 4) * IW) + w8 * 2;

    // Front-batch all 8 independent 128-bit loads (single batch, no
    // mid-thread consumption point).
    float4 a0 = r0[0 * rstep + 0];
    float4 a1 = r0[0 * rstep + 1];
    float4 b0 = r0[1 * rstep + 0];
    float4 b1 = r0[1 * rstep + 1];
    float4 c0 = r0[2 * rstep + 0];
    float4 c1 = r0[2 * rstep + 1];
    float4 d0 = r0[3 * rstep + 0];
    float4 d1 = r0[3 * rstep + 1];

    float4* orow0 = reinterpret_cast<float4*>(
        out + (size_t)nc * OUT_PLANE + (size_t)(ohp * 2) * OW) + w8;
    float4* orow1 = orow0 + (OW / 4);

    orow0[0] = pool2(a0, a1, b0, b1);
    orow1[0] = pool2(c0, c1, d0, d1);
}

extern "C" void kernel_launch(void* const* d_in, const int* in_sizes, int n_in,
                              void* d_out, int out_size) {
    const float* in = (const float*)d_in[0];
    float* out = (float*)d_out;
    int blocks = (TOTAL_THREADS + 255) / 256;   // 12544
    maxpool2d_k2s2_occ_kernel<<<blocks, 256>>>(in, out);
}

// round 12
// speedup vs baseline: 1.0093x; 1.0093x over previous
#include <cuda_runtime.h>

// MaxPool2d k=2 s=2 valid, input (32,64,224,224) fp32 -> output (32,64,112,112).
// FINAL (R2 reconfirmation): pure HBM-streaming kernel at the roofline.
// 411 MB read + 103 MB write of irreducible traffic (stride == kernel, zero
// reuse) at ~6.8 TB/s wall-clock = 85-86% of HBM3e spec. Sampled and rejected:
// 8/16 loads per thread, 256-bit LDG/STG, streaming & evict-pinned L2
// policies, persistent grid, forced occupancy — all neutral or worse on the
// timed metric. This configuration (4 independent front-batched LDG.128,
// 1 STG.128 per thread, plain cache ops) measured best.
//
// Each thread: 4 output pixels = 2x float4 loads from each of 2 input rows
// (all 16B-aligned), one float4 store. Windows disjoint; no byte read twice.

#define NC_TOTAL   2048      // 32 * 64
#define IH         224
#define IW         224
#define OH         112
#define OW         112
#define IN_PLANE   (IH * IW)         // 50176
#define OUT_PLANE  (OH * OW)         // 12544
#define GROUPS_W   (OW / 4)          // 28 float4 groups per output row
#define TOTAL_THREADS (NC_TOTAL * OH * GROUPS_W)  // 6,422,528

__global__ __launch_bounds__(256)
void maxpool2d_k2s2_kernel(const float* __restrict__ in, float* __restrict__ out) {
    int idx = blockIdx.x * blockDim.x + threadIdx.x;
    if (idx >= TOTAL_THREADS) return;

    int w8 = idx % GROUPS_W;               // which group of 4 output cols
    int t  = idx / GROUPS_W;
    int oh = t % OH;
    int nc = t / OH;

    // Input: rows oh*2 and oh*2+1, cols [w8*8, w8*8+7]
    const float4* r0 = reinterpret_cast<const float4*>(
        in + (size_t)nc * IN_PLANE + (size_t)(oh * 2) * IW) + w8 * 2;
    const float4* r1 = r0 + (IW / 4);      // next input row = 56 float4s

    // Front-batch all 4 independent 128-bit loads for MLP.
    float4 a0 = r0[0];
    float4 a1 = r0[1];
    float4 b0 = r1[0];
    float4 b1 = r1[1];

    float4 o;
    o.x = fmaxf(fmaxf(a0.x, a0.y), fmaxf(b0.x, b0.y));
    o.y = fmaxf(fmaxf(a0.z, a0.w), fmaxf(b0.z, b0.w));
    o.z = fmaxf(fmaxf(a1.x, a1.y), fmaxf(b1.x, b1.y));
    o.w = fmaxf(fmaxf(a1.z, a1.w), fmaxf(b1.z, b1.w));

    reinterpret_cast<float4*>(out + (size_t)nc * OUT_PLANE + (size_t)oh * OW)[w8] = o;
}

extern "C" void kernel_launch(void* const* d_in, const int* in_sizes, int n_in,
                              void* d_out, int out_size) {
    const float* in = (const float*)d_in[0];
    float* out = (float*)d_out;
    int blocks = (TOTAL_THREADS + 255) / 256;   // 25088
    maxpool2d_k2s2_kernel<<<blocks, 256>>>(in, out);
}

// round 13
// speedup vs baseline: 1.0114x; 1.0021x over previous
#include <cuda_runtime.h>

// MaxPool2d k=2 s=2 valid, (32,64,224,224) fp32 -> (32,64,112,112).
// R12: fully-coalesced-per-instruction variant. In R2, each LDG.128 warp
// instruction touched 8 half-used 128B lines (lanes strided 32 B). Here one
// thread = 2 output rows x 2 output cols: 4 front-batched LDG.128 from input
// rows 4*oh..4*oh+3, all at the SAME float4 column index -> lane-consecutive
// addresses -> each warp load is one contiguous 512 B (4 full lines).
// Outputs: two float2 STG.64, also lane-contiguous (256 B/warp store).
// Same thread count & bytes-in-flight as the 75.81 us baseline; only the
// per-instruction sector efficiency changes. Plain cache ops (best measured).

#define NC_TOTAL   2048              // 32 * 64
#define IH         224
#define IW         224
#define OH         112
#define OW         112
#define IN_PLANE   (IH * IW)         // 50176
#define OUT_PLANE  (OH * OW)         // 12544
#define GROUPS_W   (IW / 4)          // 56 float4 groups per input row (=2 out cols)
#define ROWPAIRS   (OH / 2)          // 56 output-row pairs
#define TOTAL_THREADS (NC_TOTAL * ROWPAIRS * GROUPS_W)   // 6,422,528

__global__ __launch_bounds__(256)
void maxpool2d_k2s2_coal_kernel(const float* __restrict__ in, float* __restrict__ out) {
    int idx = blockIdx.x * blockDim.x + threadIdx.x;
    if (idx >= TOTAL_THREADS) return;

    int g   = idx % GROUPS_W;            // float4 column index (4 input cols -> 2 out cols)
    int t   = idx / GROUPS_W;
    int ohp = t % ROWPAIRS;              // which pair of output rows
    int nc  = t / ROWPAIRS;

    const int rstep = IW / 4;            // 56 float4 per input row
    const float4* base = reinterpret_cast<const float4*>(
        in + (size_t)nc * IN_PLANE + (size_t)(ohp * 4) * IW) + g;

    // 4 front-batched, independent, per-instruction fully coalesced LDG.128.
    float4 a = base[0 * rstep];          // input row 4*ohp
    float4 b = base[1 * rstep];          // input row 4*ohp+1
    float4 c = base[2 * rstep];          // input row 4*ohp+2
    float4 d = base[3 * rstep];          // input row 4*ohp+3

    float2 o0, o1;
    o0.x = fmaxf(fmaxf(a.x, a.y), fmaxf(b.x, b.y));
    o0.y = fmaxf(fmaxf(a.z, a.w), fmaxf(b.z, b.w));
    o1.x = fmaxf(fmaxf(c.x, c.y), fmaxf(d.x, d.y));
    o1.y = fmaxf(fmaxf(c.z, c.w), fmaxf(d.z, d.w));

    float2* orow0 = reinterpret_cast<float2*>(
        out + (size_t)nc * OUT_PLANE + (size_t)(ohp * 2) * OW) + g;
    float2* orow1 = orow0 + (OW / 2);    // next output row = 56 float2

    orow0[0] = o0;
    orow1[0] = o1;
}

extern "C" void kernel_launch(void* const* d_in, const int* in_sizes, int n_in,
                              void* d_out, int out_size) {
    const float* in = (const float*)d_in[0];
    float* out = (float*)d_out;
    int blocks = (TOTAL_THREADS + 255) / 256;   // 25088
    maxpool2d_k2s2_coal_kernel<<<blocks, 256>>>(in, out);
}